// round 5
// baseline (speedup 1.0000x reference)
#include <cuda_runtime.h>

#define Bb 4
#define Tt 512
#define Cc 128
#define NEG_INF (-1e22f)

__device__ float g_q[Bb * Tt * Cc];
__device__ float g_k[Bb * Tt * Cc];
__device__ float g_sc[Bb * Tt * Tt];  // raw scores (4 MB, lives in L2)

typedef unsigned long long u64;

// ---- packed f32x2 helpers -------------------------------------------------
__device__ __forceinline__ u64 addrelu2(u64 a, u64 b) {
    u64 s;
    asm("add.rn.f32x2 %0, %1, %2;" : "=l"(s) : "l"(a), "l"(b));
    asm("{\n\t"
        ".reg .f32 lo, hi;\n\t"
        "mov.b64 {lo, hi}, %0;\n\t"
        "max.f32 lo, lo, 0f00000000;\n\t"
        "max.f32 hi, hi, 0f00000000;\n\t"
        "mov.b64 %0, {lo, hi};\n\t"
        "}"
        : "+l"(s));
    return s;
}
__device__ __forceinline__ void fma2(u64& acc, u64 a, u64 b) {
    asm("fma.rn.f32x2 %0, %1, %2, %0;" : "+l"(acc) : "l"(a), "l"(b));
}
__device__ __forceinline__ u64 add2(u64 a, u64 b) {
    u64 s;
    asm("add.rn.f32x2 %0, %1, %2;" : "=l"(s) : "l"(a), "l"(b));
    return s;
}
__device__ __forceinline__ u64 dup2(float w) {
    u64 r;
    asm("mov.b64 %0, {%1, %1};" : "=l"(r) : "f"(w));
    return r;
}
__device__ __forceinline__ float lo2(u64 a) { return __uint_as_float((unsigned)a); }
__device__ __forceinline__ float hi2(u64 a) { return __uint_as_float((unsigned)(a >> 32)); }
__device__ __forceinline__ float hsum2(u64 a) { return lo2(a) + hi2(a); }

// ---------------------------------------------------------------------------
// Kernel 1: Q/K projection. Grid (128, 2): y=0 -> Q, y=1 -> K.
// ---------------------------------------------------------------------------
__global__ void __launch_bounds__(256) qk_kernel(const float* __restrict__ x,
                                                 const float* __restrict__ WQ,
                                                 const float* __restrict__ WK) {
    __shared__ float4 xs[16 * 32];
    const int tid  = threadIdx.x;
    const int row0 = blockIdx.x * 16;
    const float* W   = blockIdx.y ? WK : WQ;
    float*       OUT = blockIdx.y ? g_k : g_q;

#pragma unroll
    for (int t = 0; t < 2; t++) {
        int f4 = tid + 256 * t;
        int r = f4 >> 5, c = f4 & 31;
        xs[f4] = ((const float4*)(x + (size_t)(row0 + r) * Cc))[c];
    }
    __syncthreads();

    const int col = tid & 127;
    const int rh  = tid >> 7;

    float acc[8];
#pragma unroll
    for (int r = 0; r < 8; r++) acc[r] = 0.f;

#pragma unroll 4
    for (int d4 = 0; d4 < 32; d4++) {
        float w0 = W[(4 * d4 + 0) * Cc + col];
        float w1 = W[(4 * d4 + 1) * Cc + col];
        float w2 = W[(4 * d4 + 2) * Cc + col];
        float w3 = W[(4 * d4 + 3) * Cc + col];
#pragma unroll
        for (int r = 0; r < 8; r++) {
            float4 xv = xs[(rh * 8 + r) * 32 + d4];
            acc[r] += xv.x * w0;
            acc[r] += xv.y * w1;
            acc[r] += xv.z * w2;
            acc[r] += xv.w * w3;
        }
    }
#pragma unroll
    for (int r = 0; r < 8; r++)
        OUT[(size_t)(row0 + rh * 8 + r) * Cc + col] = acc[r];
}

// ---------------------------------------------------------------------------
// Kernel 2: score tiles. Grid (8 jt, 8 it, 4 b) = 256 blocks, 512 threads.
// Tile 64i x 64j x 128d, fully staged. Transposed smem: [d2][row] float2.
// smem u64 layout: kt [0,4224) | qt [4224,8448) | pt [8448,8512)
// ---------------------------------------------------------------------------
#define SC_SMEM_U64 8512
#define SC_SMEM_BYTES (SC_SMEM_U64 * 8)

__global__ void __launch_bounds__(512, 2) score_kernel() {
    extern __shared__ u64 smem_u[];
    u64* ktu = smem_u;          // [64 d2][66] (i index 0..63 used)
    u64* qtu = smem_u + 4224;   // [64 d2][66]
    u64* ptu = smem_u + 8448;   // [64 d2]

    const int tid = threadIdx.x;
    const int b   = blockIdx.z;
    const int i0  = blockIdx.y * 64;
    const int j0  = blockIdx.x * 64;

    float2* ktf = (float2*)ktu;
    float2* qtf = (float2*)qtu;

    // stage K and Q tiles transposed: [d2][row]
#pragma unroll
    for (int t = 0; t < 4; t++) {
        int f4 = tid + 512 * t;  // 0..2047
        int r = f4 >> 5, c = f4 & 31;
        float4 kv = ((const float4*)(g_k + (size_t)(b * Tt + i0 + r) * Cc))[c];
        float4 qv = ((const float4*)(g_q + (size_t)(b * Tt + j0 + r) * Cc))[c];
        ktf[(2 * c + 0) * 66 + r] = make_float2(kv.x, kv.y);
        ktf[(2 * c + 1) * 66 + r] = make_float2(kv.z, kv.w);
        qtf[(2 * c + 0) * 66 + r] = make_float2(qv.x, qv.y);
        qtf[(2 * c + 1) * 66 + r] = make_float2(qv.z, qv.w);
    }
    if (tid < 32) {
        const float4 pv4 = ((const float4*)0)[0] , *pp = 0; (void)pp; (void)pv4;
    }
    __syncthreads();  // dummy guard removed below; real p staged next
    if (tid < 32) {
        // p transposed: pt[d2] = (p via g? ) -- p passed through const arg below
    }
    __syncthreads();

    const int jl = tid & 15;   // 4 j's: j0 + 4jl .. +3
    const int ig = tid >> 4;   // 0..31 -> rows i0 + 2ig, 2ig+1

    u64 acc[2][4];
#pragma unroll
    for (int ii = 0; ii < 2; ii++)
#pragma unroll
        for (int jj = 0; jj < 4; jj++) acc[ii][jj] = 0ull;

#pragma unroll 4
    for (int d2 = 0; d2 < 64; d2++) {
        u64        pv = ptu[d2];
        ulonglong2 ka = *(const ulonglong2*)(ktu + d2 * 66 + 2 * ig);
        ulonglong2 qa = *(const ulonglong2*)(qtu + d2 * 66 + 4 * jl);
        ulonglong2 qb = *(const ulonglong2*)(qtu + d2 * 66 + 4 * jl + 2);

        fma2(acc[0][0], pv, addrelu2(qa.x, ka.x));
        fma2(acc[0][1], pv, addrelu2(qa.y, ka.x));
        fma2(acc[0][2], pv, addrelu2(qb.x, ka.x));
        fma2(acc[0][3], pv, addrelu2(qb.y, ka.x));
        fma2(acc[1][0], pv, addrelu2(qa.x, ka.y));
        fma2(acc[1][1], pv, addrelu2(qa.y, ka.y));
        fma2(acc[1][2], pv, addrelu2(qb.x, ka.y));
        fma2(acc[1][3], pv, addrelu2(qb.y, ka.y));
    }

#pragma unroll
    for (int ii = 0; ii < 2; ii++) {
        float4 o;
        o.x = hsum2(acc[ii][0]);
        o.y = hsum2(acc[ii][1]);
        o.z = hsum2(acc[ii][2]);
        o.w = hsum2(acc[ii][3]);
        ((float4*)(g_sc + ((size_t)(b * Tt) + i0 + 2 * ig + ii) * Tt + j0))[jl] = o;
    }
}

// p staging needs the pointer, so wrap: a tiny variant taking p.
__global__ void __launch_bounds__(512, 2) score_kernel_p(const float* __restrict__ p) {
    extern __shared__ u64 smem_u[];
    u64* ktu = smem_u;
    u64* qtu = smem_u + 4224;
    u64* ptu = smem_u + 8448;

    const int tid = threadIdx.x;
    const int b   = blockIdx.z;
    const int i0  = blockIdx.y * 64;
    const int j0  = blockIdx.x * 64;

    float2* ktf = (float2*)ktu;
    float2* qtf = (float2*)qtu;
    float2* ptf = (float2*)ptu;

#pragma unroll
    for (int t = 0; t < 4; t++) {
        int f4 = tid + 512 * t;
        int r = f4 >> 5, c = f4 & 31;
        float4 kv = ((const float4*)(g_k + (size_t)(b * Tt + i0 + r) * Cc))[c];
        float4 qv = ((const float4*)(g_q + (size_t)(b * Tt + j0 + r) * Cc))[c];
        ktf[(2 * c + 0) * 66 + r] = make_float2(kv.x, kv.y);
        ktf[(2 * c + 1) * 66 + r] = make_float2(kv.z, kv.w);
        qtf[(2 * c + 0) * 66 + r] = make_float2(qv.x, qv.y);
        qtf[(2 * c + 1) * 66 + r] = make_float2(qv.z, qv.w);
    }
    if (tid < 32) {
        float4 pv = ((const float4*)p)[tid];
        ptf[2 * tid + 0] = make_float2(pv.x, pv.y);
        ptf[2 * tid + 1] = make_float2(pv.z, pv.w);
    }
    __syncthreads();

    const int jl = tid & 15;
    const int ig = tid >> 4;

    u64 acc[2][4];
#pragma unroll
    for (int ii = 0; ii < 2; ii++)
#pragma unroll
        for (int jj = 0; jj < 4; jj++) acc[ii][jj] = 0ull;

#pragma unroll 4
    for (int d2 = 0; d2 < 64; d2++) {
        u64        pv = ptu[d2];
        ulonglong2 ka = *(const ulonglong2*)(ktu + d2 * 66 + 2 * ig);
        ulonglong2 qa = *(const ulonglong2*)(qtu + d2 * 66 + 4 * jl);
        ulonglong2 qb = *(const ulonglong2*)(qtu + d2 * 66 + 4 * jl + 2);

        fma2(acc[0][0], pv, addrelu2(qa.x, ka.x));
        fma2(acc[0][1], pv, addrelu2(qa.y, ka.x));
        fma2(acc[0][2], pv, addrelu2(qb.x, ka.x));
        fma2(acc[0][3], pv, addrelu2(qb.y, ka.x));
        fma2(acc[1][0], pv, addrelu2(qa.x, ka.y));
        fma2(acc[1][1], pv, addrelu2(qa.y, ka.y));
        fma2(acc[1][2], pv, addrelu2(qb.x, ka.y));
        fma2(acc[1][3], pv, addrelu2(qb.y, ka.y));
    }

#pragma unroll
    for (int ii = 0; ii < 2; ii++) {
        float4 o;
        o.x = hsum2(acc[ii][0]);
        o.y = hsum2(acc[ii][1]);
        o.z = hsum2(acc[ii][2]);
        o.w = hsum2(acc[ii][3]);
        ((float4*)(g_sc + ((size_t)(b * Tt) + i0 + 2 * ig + ii) * Tt + j0))[jl] = o;
    }
}

// ---------------------------------------------------------------------------
// Kernel 3: softmax + AV. Grid (64 i-tiles of 8, 4 b) = 256 blocks, 512 thr.
// smem floats: ps8 8x512 [0,4096) | xs 128x132 [4096,20992)
// ---------------------------------------------------------------------------
#define AV_SMEM_FLOATS 20992
#define AV_SMEM_BYTES  (AV_SMEM_FLOATS * 4)
#define AJT 128

__global__ void __launch_bounds__(512, 2) av_kernel(const float* __restrict__ x,
                                                    const float* __restrict__ adj,
                                                    float* __restrict__ out) {
    extern __shared__ float smemf[];
    float* ps8 = smemf;         // 8 x 512
    float* xs  = smemf + 4096;  // 128 x 132

    const int tid  = threadIdx.x;
    const int warp = tid >> 5, lane = tid & 31;
    const int b    = blockIdx.y;
    const int i0   = blockIdx.x * 8;

    if (warp < 8) {
        // softmax of row i0+warp
        const int    r    = warp;
        const float* srow = g_sc + ((size_t)(b * Tt) + i0 + r) * Tt;
        const float* arow = adj + ((size_t)(b * Tt) + i0 + r) * Tt;
        float v[16];
        float m = -3.4e38f;
#pragma unroll
        for (int t = 0; t < 16; t++) {
            int   j = lane + 32 * t;
            float s = srow[j];
            s    = (arow[j] > 0.f) ? s : NEG_INF;
            v[t] = s;
            m    = fmaxf(m, s);
        }
#pragma unroll
        for (int o = 16; o; o >>= 1) m = fmaxf(m, __shfl_xor_sync(0xffffffff, m, o));
        float sum = 0.f;
#pragma unroll
        for (int t = 0; t < 16; t++) {
            v[t] = __expf(v[t] - m);
            sum += v[t];
        }
#pragma unroll
        for (int o = 16; o; o >>= 1) sum += __shfl_xor_sync(0xffffffff, sum, o);
        float inv = 1.f / sum;
#pragma unroll
        for (int t = 0; t < 16; t++) ps8[r * Tt + lane + 32 * t] = v[t] * inv;
    } else {
        // warps 8-15: stage x chunk 0
        int ltid = tid - 256;
#pragma unroll
        for (int t = 0; t < 16; t++) {
            int f4 = ltid + 256 * t;  // 0..4095
            int r = f4 >> 5, c = f4 & 31;
            ((float4*)(xs + r * 132))[c] =
                ((const float4*)(x + (size_t)(b * Tt + r) * Cc))[c];
        }
    }
    __syncthreads();

    const int rg = warp & 3;   // rows 2rg, 2rg+1
    const int jq = warp >> 2;  // j-quarter within chunk (32 js)

    u64 a00 = 0, a01 = 0, a10 = 0, a11 = 0;

    for (int c = 0; c < 4; c++) {
        const int jc = c * AJT;
        const float* w0p = ps8 + (2 * rg + 0) * Tt + jc + 32 * jq;
        const float* w1p = ps8 + (2 * rg + 1) * Tt + jc + 32 * jq;
#pragma unroll 4
        for (int jj = 0; jj < 32; jj++) {
            u64        w0 = dup2(w0p[jj]);
            u64        w1 = dup2(w1p[jj]);
            ulonglong2 xv = ((const ulonglong2*)(xs + (32 * jq + jj) * 132))[lane];
            fma2(a00, w0, xv.x);
            fma2(a01, w0, xv.y);
            fma2(a10, w1, xv.x);
            fma2(a11, w1, xv.y);
        }
        __syncthreads();
        if (c < 3) {
#pragma unroll
            for (int t = 0; t < 8; t++) {
                int f4 = tid + 512 * t;  // 0..4095
                int r = f4 >> 5, cc = f4 & 31;
                ((float4*)(xs + r * 132))[cc] =
                    ((const float4*)(x + (size_t)(b * Tt + jc + AJT + r) * Cc))[cc];
            }
            __syncthreads();
        }
    }

    // reduce over jq through smem (reuse xs): buf[(jq-1)*8 + row][64 u64 cols]
    u64* buf = (u64*)xs;
    if (jq != 0) {
        int base = ((jq - 1) * 8 + 2 * rg) * 64 + 2 * lane;
        buf[base + 0]      = a00;
        buf[base + 1]      = a01;
        buf[base + 64]     = a10;
        buf[base + 64 + 1] = a11;
    }
    __syncthreads();
    if (jq == 0) {
#pragma unroll
        for (int q = 0; q < 3; q++) {
            int base = (q * 8 + 2 * rg) * 64 + 2 * lane;
            a00 = add2(a00, buf[base + 0]);
            a01 = add2(a01, buf[base + 1]);
            a10 = add2(a10, buf[base + 64]);
            a11 = add2(a11, buf[base + 64 + 1]);
        }
        float4 o0 = make_float4(lo2(a00), hi2(a00), lo2(a01), hi2(a01));
        float4 o1 = make_float4(lo2(a10), hi2(a10), lo2(a11), hi2(a11));
        ((float4*)(out + ((size_t)(b * Tt) + i0 + 2 * rg + 0) * Cc))[lane] = o0;
        ((float4*)(out + ((size_t)(b * Tt) + i0 + 2 * rg + 1) * Cc))[lane] = o1;
    }
}

// ---------------------------------------------------------------------------
extern "C" void kernel_launch(void* const* d_in, const int* in_sizes, int n_in,
                              void* d_out, int out_size) {
    const float* x   = (const float*)d_in[0];
    const float* adj = (const float*)d_in[1];
    const float* WQ  = (const float*)d_in[2];
    const float* WK  = (const float*)d_in[3];
    const float* p   = (const float*)d_in[4];
    float*       out = (float*)d_out;

    qk_kernel<<<dim3((Bb * Tt) / 16, 2), 256>>>(x, WQ, WK);

    cudaFuncSetAttribute(score_kernel_p, cudaFuncAttributeMaxDynamicSharedMemorySize,
                         SC_SMEM_BYTES);
    score_kernel_p<<<dim3(Tt / 64, Tt / 64, Bb), 512, SC_SMEM_BYTES>>>(p);

    cudaFuncSetAttribute(av_kernel, cudaFuncAttributeMaxDynamicSharedMemorySize,
                         AV_SMEM_BYTES);
    av_kernel<<<dim3(Tt / 8, Bb), 512, AV_SMEM_BYTES>>>(x, adj, out);
}

// round 6
// speedup vs baseline: 1.2355x; 1.2355x over previous
#include <cuda_runtime.h>

#define Bb 4
#define Tt 512
#define Cc 128
#define NROWS (Bb * Tt)  // 2048
#define NEG_INF (-1e22f)
#define TI 8

// Q stored transposed: qT[d][global_row]; K row-major.
__device__ float g_qT[Cc * NROWS];
__device__ float g_k[NROWS * Cc];

typedef unsigned long long u64;

// ---- packed f32x2 helpers -------------------------------------------------
__device__ __forceinline__ u64 add2(u64 a, u64 b) {
    u64 s;
    asm("add.rn.f32x2 %0, %1, %2;" : "=l"(s) : "l"(a), "l"(b));
    return s;
}
__device__ __forceinline__ u64 relu2(u64 s) {
    asm("{\n\t"
        ".reg .f32 lo, hi;\n\t"
        "mov.b64 {lo, hi}, %0;\n\t"
        "max.f32 lo, lo, 0f00000000;\n\t"
        "max.f32 hi, hi, 0f00000000;\n\t"
        "mov.b64 %0, {lo, hi};\n\t"
        "}"
        : "+l"(s));
    return s;
}
__device__ __forceinline__ void fma2(u64& acc, u64 a, u64 b) {
    asm("fma.rn.f32x2 %0, %1, %2, %0;" : "+l"(acc) : "l"(a), "l"(b));
}
__device__ __forceinline__ u64 dup2(float w) {
    u64 r;
    asm("mov.b64 %0, {%1, %1};" : "=l"(r) : "f"(w));
    return r;
}

// ---------------------------------------------------------------------------
// Kernel 1: projection. Grid (16 row-tiles, 8 col-tiles, 2): z=0 Q (transposed
// output), z=1 K (row-major output). Block 256 threads: 128 rows x 16 cols,
// thread = 8 rows x 1 col.
// smem: xs4 [128][33] float4 (67.6KB) | Ws4 [16][33] float4 (8.4KB)
// ---------------------------------------------------------------------------
#define PJ_XS4   (128 * 33)
#define PJ_WS4   (16 * 33)
#define PJ_SMEM_BYTES ((PJ_XS4 + PJ_WS4) * 16)

__global__ void __launch_bounds__(256, 2) proj_kernel(const float* __restrict__ x,
                                                      const float* __restrict__ WQ,
                                                      const float* __restrict__ WK) {
    extern __shared__ float4 psm4[];
    float4* xs4 = psm4;           // [128][33]
    float4* Ws4 = psm4 + PJ_XS4;  // [16][33]  (Wst[col][d] as float4 over d)

    const int tid  = threadIdx.x;
    const int row0 = blockIdx.x * 128;
    const int c0   = blockIdx.y * 16;
    const float* W = blockIdx.z ? WK : WQ;

    // stage x tile (128 rows x 128 floats), padded rows of 33 float4
#pragma unroll
    for (int t = 0; t < 16; t++) {
        int f4 = tid + 256 * t;  // 0..4095
        int r = f4 >> 5, c = f4 & 31;
        xs4[r * 33 + c] = ((const float4*)(x + (size_t)(row0 + r) * Cc))[c];
    }
    // stage W columns c0..c0+15 transposed: Wst[col][d]
    {
        float* Wsf = (float*)Ws4;
#pragma unroll
        for (int t = 0; t < 8; t++) {
            int idx = tid + 256 * t;  // 0..2047
            int col = idx & 15, d = idx >> 4;
            Wsf[col * 132 + d] = W[(size_t)d * Cc + c0 + col];
        }
    }
    __syncthreads();

    const int col  = tid & 15;
    const int rowg = tid >> 4;  // 0..15 -> rows rowg*8 .. +7

    float acc[8];
#pragma unroll
    for (int m = 0; m < 8; m++) acc[m] = 0.f;

#pragma unroll 8
    for (int d4 = 0; d4 < 32; d4++) {
        float4 wv = Ws4[col * 33 + d4];
#pragma unroll
        for (int m = 0; m < 8; m++) {
            float4 xv = xs4[(rowg * 8 + m) * 33 + d4];
            acc[m] += xv.x * wv.x;
            acc[m] += xv.y * wv.y;
            acc[m] += xv.z * wv.z;
            acc[m] += xv.w * wv.w;
        }
    }

    if (blockIdx.z) {
        // K: row-major direct store
#pragma unroll
        for (int m = 0; m < 8; m++)
            g_k[(size_t)(row0 + rowg * 8 + m) * Cc + c0 + col] = acc[m];
    } else {
        // Q: transpose through smem (reuse xs region), coalesced qT store
        __syncthreads();
        float* tmp = (float*)xs4;  // tmp[col][132 row-pad]
#pragma unroll
        for (int m = 0; m < 8; m++) tmp[col * 132 + rowg * 8 + m] = acc[m];
        __syncthreads();

        const int warp = tid >> 5, lane = tid & 31;
#pragma unroll
        for (int cc = 0; cc < 2; cc++) {
            int c = 2 * warp + cc;
            float4 v = ((const float4*)(tmp + c * 132))[lane];
            ((float4*)(g_qT + (size_t)(c0 + c) * NROWS + row0))[lane] = v;
        }
    }
}

// ---------------------------------------------------------------------------
// Kernel 2: fused score + masked softmax + AV. Grid (64, 4), 512 threads.
// smem (u64 units): ksd [0,1024) | psd [1024,1152) | sc(float) [1152,3200)
//                   scd [3200,7296)  (scd reused as AV reduction buffer)
// ---------------------------------------------------------------------------
#define AT_SMEM_U64 7296
#define AT_SMEM_BYTES (AT_SMEM_U64 * 8)

__global__ void __launch_bounds__(512, 2) attn_kernel(const float* __restrict__ x,
                                                      const float* __restrict__ adj,
                                                      const float* __restrict__ p,
                                                      float* __restrict__ out) {
    extern __shared__ u64 asm_u[];
    u64*   ksd = asm_u;                 // [8][128] k duplicated
    u64*   psd = asm_u + 1024;          // [128]    p duplicated
    float* sc  = (float*)(asm_u + 1152);  // [8][512] raw scores
    u64*   scd = asm_u + 3200;          // [8][512] softmax weights dup'd

    const int tid = threadIdx.x;
    const int b   = blockIdx.y;
    const int i0  = blockIdx.x * TI;

    // stage k rows (dup'd) + p (dup'd)
#pragma unroll
    for (int t = 0; t < 2; t++) {
        int idx = tid + 512 * t;  // 0..1023
        int r = idx >> 7, d = idx & 127;
        ksd[r * 128 + d] = dup2(g_k[(size_t)(b * Tt + i0 + r) * Cc + d]);
    }
    if (tid < 128) psd[tid] = dup2(p[tid]);
    __syncthreads();

    // ================= score phase: thread = 2i x 4j, packed over j =========
    {
        const int ig = tid >> 7;       // 0..3 -> rows 2ig, 2ig+1
        const int j0 = (tid & 127) * 4;  // 4 consecutive j's
        const float* qb = g_qT + b * Tt + j0;

        u64 a00 = 0, a01 = 0, a10 = 0, a11 = 0;
        const u64* k0p = ksd + (2 * ig + 0) * 128;
        const u64* k1p = ksd + (2 * ig + 1) * 128;

#pragma unroll 4
        for (int d4 = 0; d4 < 32; d4++) {
#pragma unroll
            for (int e = 0; e < 4; e++) {
                int d = 4 * d4 + e;
                ulonglong2 q = *(const ulonglong2*)(qb + (size_t)d * NROWS);
                u64 pd = psd[d];
                u64 k0 = k0p[d];
                u64 k1 = k1p[d];
                fma2(a00, pd, relu2(add2(q.x, k0)));
                fma2(a01, pd, relu2(add2(q.y, k0)));
                fma2(a10, pd, relu2(add2(q.x, k1)));
                fma2(a11, pd, relu2(add2(q.y, k1)));
            }
        }
        u64* s0 = (u64*)(sc + (2 * ig + 0) * Tt + j0);
        u64* s1 = (u64*)(sc + (2 * ig + 1) * Tt + j0);
        s0[0] = a00; s0[1] = a01;
        s1[0] = a10; s1[1] = a11;
    }
    __syncthreads();

    // ================= masked softmax (warps 0-7, one row each) =============
    const int warp = tid >> 5, lane = tid & 31;
    if (warp < 8) {
        const int    r    = warp;
        const float* arow = adj + ((size_t)(b * Tt) + i0 + r) * Tt;
        float v[16];
        float m = -3.4e38f;
#pragma unroll
        for (int t = 0; t < 16; t++) {
            int   j = lane + 32 * t;
            float s = sc[r * Tt + j];
            s    = (arow[j] > 0.f) ? s : NEG_INF;
            v[t] = s;
            m    = fmaxf(m, s);
        }
#pragma unroll
        for (int o = 16; o; o >>= 1) m = fmaxf(m, __shfl_xor_sync(0xffffffff, m, o));
        float sum = 0.f;
#pragma unroll
        for (int t = 0; t < 16; t++) {
            v[t] = __expf(v[t] - m);
            sum += v[t];
        }
#pragma unroll
        for (int o = 16; o; o >>= 1) sum += __shfl_xor_sync(0xffffffff, sum, o);
        float inv = 1.f / sum;
#pragma unroll
        for (int t = 0; t < 16; t++)
            scd[r * Tt + lane + 32 * t] = dup2(v[t] * inv);
    }
    __syncthreads();

    // ================= AV: warps = 8 jq x 2 dq; thread = 8i x 2d ===========
    const int jq = warp >> 1;       // 0..7 -> 64 j's
    const int dq = warp & 1;        // 0/1 -> d half
    const int d0 = dq * 64 + 2 * lane;

    u64 av[8];
#pragma unroll
    for (int i = 0; i < 8; i++) av[i] = 0ull;

    const float* xb = x + (size_t)(b * Tt) * Cc;
#pragma unroll 4
    for (int jj = 0; jj < 64; jj++) {
        int j  = jq * 64 + jj;
        u64 xv = *(const u64*)(xb + (size_t)j * Cc + d0);
#pragma unroll
        for (int i = 0; i < 8; i++) fma2(av[i], scd[i * Tt + j], xv);
    }
    __syncthreads();

    // reduce over jq through smem (reuse scd region)
    u64* buf = scd;  // 7 * 8 * 64 u64 = 28KB <= 32KB
    if (jq != 0) {
#pragma unroll
        for (int i = 0; i < 8; i++)
            buf[((jq - 1) * 8 + i) * 64 + dq * 32 + lane] = av[i];
    }
    __syncthreads();
    if (jq == 0) {
#pragma unroll
        for (int q = 0; q < 7; q++)
#pragma unroll
            for (int i = 0; i < 8; i++)
                av[i] = add2(av[i], buf[(q * 8 + i) * 64 + dq * 32 + lane]);
#pragma unroll
        for (int i = 0; i < 8; i++)
            *(u64*)(out + (size_t)(b * Tt + i0 + i) * Cc + d0) = av[i];
    }
}

// ---------------------------------------------------------------------------
extern "C" void kernel_launch(void* const* d_in, const int* in_sizes, int n_in,
                              void* d_out, int out_size) {
    const float* x   = (const float*)d_in[0];
    const float* adj = (const float*)d_in[1];
    const float* WQ  = (const float*)d_in[2];
    const float* WK  = (const float*)d_in[3];
    const float* p   = (const float*)d_in[4];
    float*       out = (float*)d_out;

    cudaFuncSetAttribute(proj_kernel, cudaFuncAttributeMaxDynamicSharedMemorySize,
                         PJ_SMEM_BYTES);
    proj_kernel<<<dim3(NROWS / 128, Cc / 16, 2), 256, PJ_SMEM_BYTES>>>(x, WQ, WK);

    cudaFuncSetAttribute(attn_kernel, cudaFuncAttributeMaxDynamicSharedMemorySize,
                         AT_SMEM_BYTES);
    attn_kernel<<<dim3(Tt / TI, Bb), 512, AT_SMEM_BYTES>>>(x, adj, p, out);
}